// round 1
// baseline (speedup 1.0000x reference)
#include <cuda_runtime.h>
#include <cstdint>
#include <math.h>

#define Bdim 4
#define Sdim 2048
#define Ddim 512
#define Hdim 8

// Scratch (device globals: allocation-free, harness-legal)
__device__ float g_q[(size_t)Bdim * Hdim * Sdim * Ddim];   // 128 MB
__device__ float g_k[(size_t)Bdim * Hdim * Sdim * Ddim];   // 128 MB
__device__ float g_v[(size_t)Bdim * Hdim * Sdim * Ddim];   // 128 MB
__device__ float g_p[(size_t)Bdim * Hdim * Sdim * Sdim];   // 512 MB (logits/probs)
__device__ float g_c[(size_t)Bdim * Sdim * Hdim * Ddim];   // 128 MB (concat)

__device__ __forceinline__ uint32_t f2tf(float f) {
    uint32_t r;
    asm("cvt.rna.tf32.f32 %0, %1;" : "=r"(r) : "f"(f));
    return r;
}

__device__ __forceinline__ void mma8(float* c, const uint32_t* a, const uint32_t* b) {
    asm volatile(
        "mma.sync.aligned.m16n8k8.row.col.f32.tf32.tf32.f32 "
        "{%0,%1,%2,%3}, {%4,%5,%6,%7}, {%8,%9}, {%0,%1,%2,%3};\n"
        : "+f"(c[0]), "+f"(c[1]), "+f"(c[2]), "+f"(c[3])
        : "r"(a[0]), "r"(a[1]), "r"(a[2]), "r"(a[3]), "r"(b[0]), "r"(b[1]));
}

// Generic batched GEMM:  C[M,N] = alpha * A[M,K] * op(B)
//   BT=true : B is [N,K] row-major (K-contiguous), computes A*B^T   ("NT")
//   BT=false: B is [K,N] row-major (N-contiguous), computes A*B     ("NN")
// blockIdx.z = batch slice; z1 = z / Z2, z2 = z % Z2; per-operand offsets
// offX = z1*sX1 + z2*sX2. CTA tile 128x128, K-chunk 32, 256 threads, 8 warps
// each computing a 32x64 warp tile of m16n8k8 tf32 MMAs.
// All M,N assumed multiples of 128, K multiple of 32 (true for every call here).
template <bool BT>
__global__ void __launch_bounds__(256)
gemm_tf32(const float* __restrict__ A, const float* __restrict__ Bm,
          float* __restrict__ C,
          int K, int lda, int ldb, int ldc, int Z2,
          long sA1, long sA2, long sB1, long sB2, long sC1, long sC2,
          float alpha)
{
    __shared__ uint32_t As[32][132];  // [k][m], padded
    __shared__ uint32_t Bs[32][132];  // [k][n], padded

    const int z = blockIdx.z, z1 = z / Z2, z2 = z % Z2;
    A  += z1 * sA1 + z2 * sA2;
    Bm += z1 * sB1 + z2 * sB2;
    C  += z1 * sC1 + z2 * sC2;

    const int bm = blockIdx.y * 128;
    const int bn = blockIdx.x * 128;
    const int tid = threadIdx.x;
    const int wid = tid >> 5, lane = tid & 31;
    const int g = lane >> 2, t4 = lane & 3;
    const int wm = (wid & 3) * 32, wn = (wid >> 2) * 64;

    // global->smem load mapping (float4 per thread, 4 iterations)
    const int arow = tid >> 3;            // 0..31
    const int af4  = (tid & 7) * 4;       // k offset 0..28
    const int bk   = tid >> 5;            // 0..7  (NN path)
    const int bn4  = (tid & 31) * 4;      // n offset 0..124 (NN path)

    float acc[2][8][4];
#pragma unroll
    for (int mt = 0; mt < 2; mt++)
#pragma unroll
        for (int nt = 0; nt < 8; nt++)
#pragma unroll
            for (int q = 0; q < 4; q++) acc[mt][nt][q] = 0.f;

    float4 pa[4], pb[4];
#pragma unroll
    for (int i = 0; i < 4; i++)
        pa[i] = *(const float4*)(A + (long)(bm + arow + i * 32) * lda + af4);
    if (BT) {
#pragma unroll
        for (int i = 0; i < 4; i++)
            pb[i] = *(const float4*)(Bm + (long)(bn + arow + i * 32) * ldb + af4);
    } else {
#pragma unroll
        for (int i = 0; i < 4; i++)
            pb[i] = *(const float4*)(Bm + (long)(bk + i * 8) * ldb + bn + bn4);
    }

    const int KC = K >> 5;
    for (int kc = 0; kc < KC; kc++) {
        // stage prefetched tile into smem (convert to tf32 once)
#pragma unroll
        for (int i = 0; i < 4; i++) {
            As[af4 + 0][arow + i * 32] = f2tf(pa[i].x);
            As[af4 + 1][arow + i * 32] = f2tf(pa[i].y);
            As[af4 + 2][arow + i * 32] = f2tf(pa[i].z);
            As[af4 + 3][arow + i * 32] = f2tf(pa[i].w);
        }
        if (BT) {
#pragma unroll
            for (int i = 0; i < 4; i++) {
                Bs[af4 + 0][arow + i * 32] = f2tf(pb[i].x);
                Bs[af4 + 1][arow + i * 32] = f2tf(pb[i].y);
                Bs[af4 + 2][arow + i * 32] = f2tf(pb[i].z);
                Bs[af4 + 3][arow + i * 32] = f2tf(pb[i].w);
            }
        } else {
#pragma unroll
            for (int i = 0; i < 4; i++) {
                uint4 u = make_uint4(f2tf(pb[i].x), f2tf(pb[i].y),
                                     f2tf(pb[i].z), f2tf(pb[i].w));
                *(uint4*)&Bs[bk + i * 8][bn4] = u;
            }
        }
        __syncthreads();

        // prefetch next K-chunk (hidden under the MMA work below)
        if (kc + 1 < KC) {
            const int ko = (kc + 1) * 32;
#pragma unroll
            for (int i = 0; i < 4; i++)
                pa[i] = *(const float4*)(A + (long)(bm + arow + i * 32) * lda + ko + af4);
            if (BT) {
#pragma unroll
                for (int i = 0; i < 4; i++)
                    pb[i] = *(const float4*)(Bm + (long)(bn + arow + i * 32) * ldb + ko + af4);
            } else {
#pragma unroll
                for (int i = 0; i < 4; i++)
                    pb[i] = *(const float4*)(Bm + (long)(ko + bk + i * 8) * ldb + bn + bn4);
            }
        }

        // 4 k-steps of 8
#pragma unroll
        for (int ks = 0; ks < 4; ks++) {
            const int kk = ks * 8;
            uint32_t af[2][4], bf[8][2];
#pragma unroll
            for (int mt = 0; mt < 2; mt++) {
                const int m0 = wm + mt * 16 + g;
                af[mt][0] = As[kk + t4][m0];
                af[mt][1] = As[kk + t4][m0 + 8];
                af[mt][2] = As[kk + t4 + 4][m0];
                af[mt][3] = As[kk + t4 + 4][m0 + 8];
            }
#pragma unroll
            for (int nt = 0; nt < 8; nt++) {
                const int n0 = wn + nt * 8 + g;
                bf[nt][0] = Bs[kk + t4][n0];
                bf[nt][1] = Bs[kk + t4 + 4][n0];
            }
#pragma unroll
            for (int mt = 0; mt < 2; mt++)
#pragma unroll
                for (int nt = 0; nt < 8; nt++)
                    mma8(acc[mt][nt], af[mt], bf[nt]);
        }
        __syncthreads();
    }

    // epilogue
#pragma unroll
    for (int mt = 0; mt < 2; mt++) {
#pragma unroll
        for (int nt = 0; nt < 8; nt++) {
            const int r0 = bm + wm + mt * 16 + g;
            const int c0 = bn + wn + nt * 8 + t4 * 2;
            C[(long)r0 * ldc + c0]           = alpha * acc[mt][nt][0];
            C[(long)r0 * ldc + c0 + 1]       = alpha * acc[mt][nt][1];
            C[(long)(r0 + 8) * ldc + c0]     = alpha * acc[mt][nt][2];
            C[(long)(r0 + 8) * ldc + c0 + 1] = alpha * acc[mt][nt][3];
        }
    }
}

// Row-wise masked softmax over [B*H*S, S] (in place). One 256-thread CTA per row.
__global__ void softmax_kernel(float* __restrict__ P, const int* __restrict__ mask)
{
    const int row = blockIdx.x;            // (b*H + h)*S + i
    const int b = row >> 14;               // / (H*S = 16384)
    const int i = row & (Sdim - 1);
    float* p = P + (size_t)row * Sdim;
    const int* mb = mask + b * Sdim;
    const int mi = mb[i];
    const int tid = threadIdx.x;

    float v[8];
    float mx = -1e30f;
#pragma unroll
    for (int l = 0; l < 8; l++) {
        const int j = tid + l * 256;
        float x = p[j];
        if (!(mi * mb[j] > 0)) x = -1e9f;
        v[l] = x;
        mx = fmaxf(mx, x);
    }

    __shared__ float red[32];
    for (int o = 16; o > 0; o >>= 1) mx = fmaxf(mx, __shfl_xor_sync(0xffffffffu, mx, o));
    if ((tid & 31) == 0) red[tid >> 5] = mx;
    __syncthreads();
    if (tid < 32) {
        float m2 = (tid < 8) ? red[tid] : -1e30f;
        for (int o = 4; o > 0; o >>= 1) m2 = fmaxf(m2, __shfl_xor_sync(0xffffffffu, m2, o));
        if (tid == 0) red[0] = m2;
    }
    __syncthreads();
    mx = red[0];
    __syncthreads();

    float s = 0.f;
#pragma unroll
    for (int l = 0; l < 8; l++) {
        const float e = expf(v[l] - mx);
        v[l] = e;
        s += e;
    }
    for (int o = 16; o > 0; o >>= 1) s += __shfl_xor_sync(0xffffffffu, s, o);
    if ((tid & 31) == 0) red[tid >> 5] = s;
    __syncthreads();
    if (tid < 32) {
        float s2 = (tid < 8) ? red[tid] : 0.f;
        for (int o = 4; o > 0; o >>= 1) s2 += __shfl_xor_sync(0xffffffffu, s2, o);
        if (tid == 0) red[0] = s2;
    }
    __syncthreads();
    const float inv = 1.0f / red[0];
#pragma unroll
    for (int l = 0; l < 8; l++) p[tid + l * 256] = v[l] * inv;
}

extern "C" void kernel_launch(void* const* d_in, const int* in_sizes, int n_in,
                              void* d_out, int out_size)
{
    (void)in_sizes; (void)n_in; (void)out_size;
    const float* x    = (const float*)d_in[0];
    const int*   mask = (const int*)d_in[1];
    const float* Wq   = (const float*)d_in[2];
    const float* Wk   = (const float*)d_in[3];
    const float* Wv   = (const float*)d_in[4];
    const float* Wp   = (const float*)d_in[5];
    float* out = (float*)d_out;

    float *q, *k, *v, *p, *c;
    cudaGetSymbolAddress((void**)&q, g_q);
    cudaGetSymbolAddress((void**)&k, g_k);
    cudaGetSymbolAddress((void**)&v, g_v);
    cudaGetSymbolAddress((void**)&p, g_p);
    cudaGetSymbolAddress((void**)&c, g_c);

    const long SD = (long)Sdim * Ddim;      // 1048576
    const long DD = (long)Ddim * Ddim;      // 262144
    const long SS = (long)Sdim * Sdim;      // 4194304
    const float scale = 1.0f / sqrtf((float)Ddim);
    dim3 blk(256);

    // 1) QKV projections: per (h,b): q[b,h,s,e] = sum_d x[b,s,d] * W[h,e,d]  (NT)
    //    z1 = h (Z2=4), z2 = b
    {
        dim3 grid(Ddim / 128, Sdim / 128, Hdim * Bdim);
        gemm_tf32<true><<<grid, blk>>>(x, Wq, q, Ddim, Ddim, Ddim, Ddim, Bdim,
                                       0, SD, DD, 0, SD, Hdim * SD, 1.f);
        gemm_tf32<true><<<grid, blk>>>(x, Wk, k, Ddim, Ddim, Ddim, Ddim, Bdim,
                                       0, SD, DD, 0, SD, Hdim * SD, 1.f);
        gemm_tf32<true><<<grid, blk>>>(x, Wv, v, Ddim, Ddim, Ddim, Ddim, Bdim,
                                       0, SD, DD, 0, SD, Hdim * SD, 1.f);
    }

    // 2) logits: L[s,t] = scale * sum_e q[s,e] k[t,e]   (NT), z = b*H+h
    {
        dim3 grid(Sdim / 128, Sdim / 128, Bdim * Hdim);
        gemm_tf32<true><<<grid, blk>>>(q, k, p, Ddim, Ddim, Ddim, Sdim, 1,
                                       SD, 0, SD, 0, SS, 0, scale);
    }

    // 3) masked softmax in place over last dim
    softmax_kernel<<<Bdim * Hdim * Sdim, blk>>>(p, mask);

    // 4) PV: O[s,e] = sum_t P[s,t] v[t,e] (NN), written directly into concat
    //    layout cat[b][s][h*D+e] (ldc=4096). z1 = b (Z2=8), z2 = h.
    {
        dim3 grid(Ddim / 128, Sdim / 128, Bdim * Hdim);
        gemm_tf32<false><<<grid, blk>>>(p, v, c, Sdim, Sdim, Ddim, Hdim * Ddim, Hdim,
                                        8 * SS, SS, Hdim * SD, SD,
                                        (long)Sdim * Hdim * Ddim, (long)Ddim, 1.f);
    }

    // 5) output projection: y[b,s,d] = sum_f cat[b,s,f] Wp[d,f]  (NT), z = b
    {
        dim3 grid(Ddim / 128, Sdim / 128, Bdim);
        gemm_tf32<true><<<grid, blk>>>(c, Wp, out, Hdim * Ddim,
                                       Hdim * Ddim, Hdim * Ddim, Ddim, 1,
                                       (long)Sdim * Hdim * Ddim, 0, 0, 0,
                                       (long)Sdim * Ddim, 0, 1.f);
    }
}

// round 3
// speedup vs baseline: 1.6835x; 1.6835x over previous
#include <cuda_runtime.h>
#include <cstdint>
#include <math.h>

#define Bdim 4
#define Sdim 2048
#define Ddim 512
#define Hdim 8

// Scratch (device globals: allocation-free)
__device__ float g_q[(size_t)Bdim * Hdim * Sdim * Ddim];   // [b][h][s][e]
__device__ float g_k[(size_t)Bdim * Hdim * Sdim * Ddim];   // [b][h][t][e]
__device__ float g_v[(size_t)Bdim * Hdim * Sdim * Ddim];   // V^T: [b][h][e][t]
__device__ float g_p[(size_t)Bdim * Hdim * Sdim * Sdim];   // [b][h][s][t]
__device__ float g_c[(size_t)Bdim * Sdim * Hdim * Ddim];   // concat [b][s][h*D+e]

// ---------------- tf32 mma.sync GEMM (all-NT) ----------------
// C[M,N] = alpha * A[M,K] * B^T   (A: [M][K] row-major, B: [N][K] row-major)
// CTA tile 128x128, 128 threads (4 warps, 2x2), warp tile 64x64.
// K-chunk 32, double-buffered smem via cp.async.cg.
// Smem layout: [row][36 floats] (32 K + 4 pad) -> conflict-free LDS + staging.

#define PITCH 36
#define TILE_F (128 * PITCH)               // floats per tile
#define SM_A0 0
#define SM_B0 (TILE_F)
#define SM_A1 (2 * TILE_F)
#define SM_B1 (3 * TILE_F)
#define SM_TOTAL (4 * TILE_F * 4)          // bytes = 73728

__device__ __forceinline__ uint32_t smem_u32(const void* p) {
    uint32_t a;
    asm("{ .reg .u64 t; cvta.to.shared.u64 t, %1; cvt.u32.u64 %0, t; }"
        : "=r"(a) : "l"(p));
    return a;
}

__device__ __forceinline__ uint32_t f2tf(float f) {
    uint32_t r;
    asm("cvt.rna.tf32.f32 %0, %1;" : "=r"(r) : "f"(f));
    return r;
}

__device__ __forceinline__ void cpasync16(uint32_t dst, const void* src) {
    asm volatile("cp.async.cg.shared.global [%0], [%1], 16;"
                 :: "r"(dst), "l"(src) : "memory");
}

__device__ __forceinline__ void mma8(float* c, const uint32_t* a, const uint32_t* b) {
    asm volatile(
        "mma.sync.aligned.m16n8k8.row.col.f32.tf32.tf32.f32 "
        "{%0,%1,%2,%3}, {%4,%5,%6,%7}, {%8,%9}, {%0,%1,%2,%3};\n"
        : "+f"(c[0]), "+f"(c[1]), "+f"(c[2]), "+f"(c[3])
        : "r"(a[0]), "r"(a[1]), "r"(a[2]), "r"(a[3]), "r"(b[0]), "r"(b[1]));
}

// stage one 128x32 tile chunk via 8 cp.async per thread
__device__ __forceinline__ void stage_async(const float* __restrict__ gbase,
                                            long ld, int kofs,
                                            uint32_t smbase, int tid) {
#pragma unroll
    for (int i = 0; i < 8; i++) {
        const int idx = tid + i * 128;
        const int m = idx >> 3;            // 0..127
        const int c = idx & 7;             // 16B chunk within 128B row
        cpasync16(smbase + (uint32_t)(m * PITCH + c * 4) * 4u,
                  gbase + (long)m * ld + kofs + c * 4);
    }
}

__global__ void __launch_bounds__(128, 2)
gemm_tc(const float* __restrict__ A, const float* __restrict__ Bm,
        float* __restrict__ C,
        int K, int lda, int ldb, int ldc, int Z2,
        long sA1, long sA2, long sB1, long sB2, long sC1, long sC2,
        float alpha)
{
    extern __shared__ float smem[];
    const uint32_t sb = smem_u32(smem);
    const int tid = threadIdx.x;
    const int wid = tid >> 5, lane = tid & 31;
    const int g = lane >> 2, t4 = lane & 3;
    const int wm = (wid & 1) * 64, wn = (wid >> 1) * 64;

    const int z = blockIdx.z, z1 = z / Z2, z2 = z % Z2;
    A  += z1 * sA1 + z2 * sA2;
    Bm += z1 * sB1 + z2 * sB2;
    C  += z1 * sC1 + z2 * sC2;
    const int bm = blockIdx.y * 128;
    const int bn = blockIdx.x * 128;

    const float* Ag = A + (long)bm * lda;
    const float* Bg = Bm + (long)bn * ldb;

    const uint32_t sA[2] = { sb + SM_A0 * 4u, sb + SM_A1 * 4u };
    const uint32_t sBf[2] = { sb + SM_B0 * 4u, sb + SM_B1 * 4u };
    const int smA[2] = { SM_A0, SM_A1 };
    const int smB[2] = { SM_B0, SM_B1 };

    float acc[4][8][4];
#pragma unroll
    for (int mt = 0; mt < 4; mt++)
#pragma unroll
        for (int nt = 0; nt < 8; nt++)
#pragma unroll
            for (int q = 0; q < 4; q++) acc[mt][nt][q] = 0.f;

    const int KC = K >> 5;

    // prologue: chunks 0 and 1
    stage_async(Ag, lda, 0, sA[0], tid);
    stage_async(Bg, ldb, 0, sBf[0], tid);
    asm volatile("cp.async.commit_group;" ::: "memory");
    if (KC > 1) {
        stage_async(Ag, lda, 32, sA[1], tid);
        stage_async(Bg, ldb, 32, sBf[1], tid);
    }
    asm volatile("cp.async.commit_group;" ::: "memory");

    for (int c = 0; c < KC; c++) {
        const int buf = c & 1;
        if (c + 1 < KC)
            asm volatile("cp.async.wait_group 1;" ::: "memory");
        else
            asm volatile("cp.async.wait_group 0;" ::: "memory");
        __syncthreads();

        const float* As = smem + smA[buf];
        const float* Bs = smem + smB[buf];

#pragma unroll
        for (int ks = 0; ks < 4; ks++) {
            const int kk = ks * 8;
            uint32_t af[4][4], bf[8][2];
#pragma unroll
            for (int mt = 0; mt < 4; mt++) {
                const int m0 = wm + mt * 16 + g;
                af[mt][0] = f2tf(As[m0 * PITCH + kk + t4]);
                af[mt][1] = f2tf(As[(m0 + 8) * PITCH + kk + t4]);
                af[mt][2] = f2tf(As[m0 * PITCH + kk + t4 + 4]);
                af[mt][3] = f2tf(As[(m0 + 8) * PITCH + kk + t4 + 4]);
            }
#pragma unroll
            for (int nt = 0; nt < 8; nt++) {
                const int n0 = wn + nt * 8 + g;
                bf[nt][0] = f2tf(Bs[n0 * PITCH + kk + t4]);
                bf[nt][1] = f2tf(Bs[n0 * PITCH + kk + t4 + 4]);
            }
#pragma unroll
            for (int mt = 0; mt < 4; mt++)
#pragma unroll
                for (int nt = 0; nt < 8; nt++)
                    mma8(acc[mt][nt], af[mt], bf[nt]);
        }
        __syncthreads();

        if (c + 2 < KC) {
            stage_async(Ag, lda, (c + 2) * 32, sA[buf], tid);
            stage_async(Bg, ldb, (c + 2) * 32, sBf[buf], tid);
        }
        asm volatile("cp.async.commit_group;" ::: "memory");
    }

    // epilogue: STG.64 pairs
#pragma unroll
    for (int mt = 0; mt < 4; mt++) {
#pragma unroll
        for (int nt = 0; nt < 8; nt++) {
            const int r0 = bm + wm + mt * 16 + g;
            const int c0 = bn + wn + nt * 8 + t4 * 2;
            float2 v0 = make_float2(alpha * acc[mt][nt][0], alpha * acc[mt][nt][1]);
            float2 v1 = make_float2(alpha * acc[mt][nt][2], alpha * acc[mt][nt][3]);
            *(float2*)&C[(long)r0 * ldc + c0] = v0;
            *(float2*)&C[(long)(r0 + 8) * ldc + c0] = v1;
        }
    }
}

// ---------------- masked softmax ----------------
__global__ void softmax_kernel(float* __restrict__ P, const int* __restrict__ mask)
{
    const int row = blockIdx.x;            // (b*H + h)*S + i
    const int b = row >> 14;               // / (H*S = 16384)
    const int i = row & (Sdim - 1);
    float* p = P + (size_t)row * Sdim;
    const int* mb = mask + b * Sdim;
    const int mi = mb[i];
    const int tid = threadIdx.x;

    float v[8];
    float mx = -1e30f;
#pragma unroll
    for (int l = 0; l < 8; l++) {
        const int j = tid + l * 256;
        float x = p[j];
        if (!(mi * mb[j] > 0)) x = -1e9f;
        v[l] = x;
        mx = fmaxf(mx, x);
    }

    __shared__ float red[32];
    for (int o = 16; o > 0; o >>= 1) mx = fmaxf(mx, __shfl_xor_sync(0xffffffffu, mx, o));
    if ((tid & 31) == 0) red[tid >> 5] = mx;
    __syncthreads();
    if (tid < 32) {
        float m2 = (tid < 8) ? red[tid] : -1e30f;
        for (int o = 4; o > 0; o >>= 1) m2 = fmaxf(m2, __shfl_xor_sync(0xffffffffu, m2, o));
        if (tid == 0) red[0] = m2;
    }
    __syncthreads();
    mx = red[0];
    __syncthreads();

    float s = 0.f;
#pragma unroll
    for (int l = 0; l < 8; l++) {
        const float e = expf(v[l] - mx);
        v[l] = e;
        s += e;
    }
    for (int o = 16; o > 0; o >>= 1) s += __shfl_xor_sync(0xffffffffu, s, o);
    if ((tid & 31) == 0) red[tid >> 5] = s;
    __syncthreads();
    if (tid < 32) {
        float s2 = (tid < 8) ? red[tid] : 0.f;
        for (int o = 4; o > 0; o >>= 1) s2 += __shfl_xor_sync(0xffffffffu, s2, o);
        if (tid == 0) red[0] = s2;
    }
    __syncthreads();
    const float inv = 1.0f / red[0];
#pragma unroll
    for (int l = 0; l < 8; l++) p[tid + l * 256] = v[l] * inv;
}

// ---------------- launcher ----------------
extern "C" void kernel_launch(void* const* d_in, const int* in_sizes, int n_in,
                              void* d_out, int out_size)
{
    (void)in_sizes; (void)n_in; (void)out_size;
    const float* x    = (const float*)d_in[0];
    const int*   mask = (const int*)d_in[1];
    const float* Wq   = (const float*)d_in[2];
    const float* Wk   = (const float*)d_in[3];
    const float* Wv   = (const float*)d_in[4];
    const float* Wp   = (const float*)d_in[5];
    float* out = (float*)d_out;

    float *q, *k, *v, *p, *c;
    cudaGetSymbolAddress((void**)&q, g_q);
    cudaGetSymbolAddress((void**)&k, g_k);
    cudaGetSymbolAddress((void**)&v, g_v);
    cudaGetSymbolAddress((void**)&p, g_p);
    cudaGetSymbolAddress((void**)&c, g_c);

    cudaFuncSetAttribute(gemm_tc, cudaFuncAttributeMaxDynamicSharedMemorySize, SM_TOTAL);

    const long SD = (long)Sdim * Ddim;      // 1048576
    const long DD = (long)Ddim * Ddim;      // 262144
    const long SS = (long)Sdim * Sdim;      // 4194304
    const float scale = 1.0f / sqrtf((float)Ddim);
    dim3 blk(128);

    // 1) Q,K projections: per (h,b): q[b,h,s,e] = x[b] @ Wq[h]^T
    //    M=S, N=D, K=D ; z1=h (Z2=B), z2=b
    {
        dim3 grid(Ddim / 128, Sdim / 128, Hdim * Bdim);
        gemm_tc<<<grid, blk, SM_TOTAL>>>(x, Wq, q, Ddim, Ddim, Ddim, Ddim, Bdim,
                                         0, SD, DD, 0, SD, Hdim * SD, 1.f);
        gemm_tc<<<grid, blk, SM_TOTAL>>>(x, Wk, k, Ddim, Ddim, Ddim, Ddim, Bdim,
                                         0, SD, DD, 0, SD, Hdim * SD, 1.f);
    }

    // 2) V^T: v_t[b,h,e,t] = Wv[h] @ x[b]^T : M=D(e), N=S(t), K=D
    {
        dim3 grid(Sdim / 128, Ddim / 128, Hdim * Bdim);
        gemm_tc<<<grid, blk, SM_TOTAL>>>(Wv, x, v, Ddim, Ddim, Ddim, Sdim, Bdim,
                                         DD, 0, 0, SD, SD, Hdim * SD, 1.f);
    }

    // 3) logits: L[s,t] = scale * q[b,h] @ k[b,h]^T : M=N=S, K=D ; z=b*H+h
    {
        dim3 grid(Sdim / 128, Sdim / 128, Bdim * Hdim);
        gemm_tc<<<grid, blk, SM_TOTAL>>>(q, k, p, Ddim, Ddim, Ddim, Sdim, 1,
                                         SD, 0, SD, 0, SS, 0, scale);
    }

    // 4) masked softmax in place
    softmax_kernel<<<Bdim * Hdim * Sdim, 256>>>(p, mask);

    // 5) PV: O[s,e] = P[b,h] @ v_t[b,h]^T : M=S, N=D, K=S -> concat layout
    //    z1=b (Z2=H), z2=h ; ldc=H*D, col offset h*D
    {
        dim3 grid(Ddim / 128, Sdim / 128, Bdim * Hdim);
        gemm_tc<<<grid, blk, SM_TOTAL>>>(p, v, c, Sdim, Sdim, Sdim, Hdim * Ddim, Hdim,
                                         (long)Hdim * SS, SS, (long)Hdim * SD, SD,
                                         (long)Sdim * Hdim * Ddim, (long)Ddim, 1.f);
    }

    // 6) out proj: y[b,s,d] = cat[b] @ Wp^T : M=S, N=D, K=H*D ; z=b
    {
        dim3 grid(Ddim / 128, Sdim / 128, Bdim);
        gemm_tc<<<grid, blk, SM_TOTAL>>>(c, Wp, out, Hdim * Ddim,
                                         Hdim * Ddim, Hdim * Ddim, Ddim, 1,
                                         (long)Sdim * Hdim * Ddim, 0, 0, 0,
                                         SD, 0, 1.f);
    }
}